// round 1
// baseline (speedup 1.0000x reference)
#include <cuda_runtime.h>

// ---------------------------------------------------------------------------
// QuantumHybridHead: 4-qubit circuit, B=524288 samples.
// Per sample: |psi> = kron(u0(w0), u1(w1), u2_const, u3(w3)) where
//   u_q = G_q * (encoder_q |0>), G_q = Rz(th[3q+2]) Ry(th[3q+1]) Rx(th[3q]).
// Wire-2 encoder rz is a global phase on |0> -> dead input.
// CNOT ring = static permutation of 16 basis amplitudes.
// Final per-wire rx(th[12+q]) gates, then <Z_w> from probabilities.
// ---------------------------------------------------------------------------

struct Cpx { float re, im; };

__device__ __forceinline__ Cpx cmul(Cpx a, Cpx b) {
    Cpx r;
    r.re = a.re * b.re - a.im * b.im;
    r.im = a.re * b.im + a.im * b.re;
    return r;
}

// Constant table computed from theta on-device:
// [0..7]   G0: g00.re g00.im g01.re g01.im g10.re g10.im g11.re g11.im
// [8..15]  G1 (same layout)
// [16..19] u2 = G2[:,0]: re im re im
// [20..27] G3
// [28..35] (cf, sf) for final rx on wires 0..3
__device__ float d_const[36];

__global__ void precompute_kernel(const float* __restrict__ theta) {
    if (threadIdx.x != 0 || blockIdx.x != 0) return;
    float G[4][8];
    #pragma unroll
    for (int q = 0; q < 4; q++) {
        float tx = theta[3 * q + 0];
        float ty = theta[3 * q + 1];
        float tz = theta[3 * q + 2];
        float cx, sx, cy, sy, cz, sz;
        sincosf(0.5f * tx, &sx, &cx);
        sincosf(0.5f * ty, &sy, &cy);
        sincosf(0.5f * tz, &sz, &cz);
        // M = Ry * Rx
        Cpx m00 = { cy * cx,  sy * sx };
        Cpx m01 = { -sy * cx, -cy * sx };
        Cpx m10 = { sy * cx,  -cy * sx };
        Cpx m11 = { cy * cx,  -sy * sx };
        // G = Rz * M ; Rz = diag(e^{-iz/2}, e^{+iz/2})
        Cpx e0 = { cz, -sz };
        Cpx e1 = { cz,  sz };
        Cpx g00 = cmul(e0, m00), g01 = cmul(e0, m01);
        Cpx g10 = cmul(e1, m10), g11 = cmul(e1, m11);
        G[q][0] = g00.re; G[q][1] = g00.im; G[q][2] = g01.re; G[q][3] = g01.im;
        G[q][4] = g10.re; G[q][5] = g10.im; G[q][6] = g11.re; G[q][7] = g11.im;
    }
    #pragma unroll
    for (int k = 0; k < 8; k++) d_const[k] = G[0][k];
    #pragma unroll
    for (int k = 0; k < 8; k++) d_const[8 + k] = G[1][k];
    // u2 = first column of G2 (wire-2 encoder is identity up to global phase)
    d_const[16] = G[2][0]; d_const[17] = G[2][1];
    d_const[18] = G[2][4]; d_const[19] = G[2][5];
    #pragma unroll
    for (int k = 0; k < 8; k++) d_const[20 + k] = G[3][k];
    #pragma unroll
    for (int q = 0; q < 4; q++) {
        float c, s;
        sincosf(0.5f * theta[12 + q], &s, &c);
        d_const[28 + 2 * q] = c;
        d_const[29 + 2 * q] = s;
    }
}

__global__ void __launch_bounds__(256)
qsim_kernel(const float4* __restrict__ inp, float4* __restrict__ out, int n) {
    int tid = blockIdx.x * blockDim.x + threadIdx.x;
    if (tid >= n) return;

    float C[36];
    #pragma unroll
    for (int k = 0; k < 36; k++) C[k] = d_const[k];

    float4 w = inp[tid];
    float c0, s0, c1, s1, c3, s3;
    __sincosf(0.5f * w.x, &s0, &c0);
    __sincosf(0.5f * w.y, &s1, &c1);
    __sincosf(0.5f * w.w, &s3, &c3);
    // w.z (wire-2 rz on |0>) is a global phase: dead.

    // Per-wire post-G vectors.
    // u0 = c0 * G0[:,0] + (-i s0) * G0[:,1]
    Cpx u0[2], u1[2], u2[2], u3[2];
    u0[0].re = c0 * C[0] + s0 * C[3];   u0[0].im = c0 * C[1] - s0 * C[2];
    u0[1].re = c0 * C[4] + s0 * C[7];   u0[1].im = c0 * C[5] - s0 * C[6];
    // u1 = c1 * G1[:,0] + s1 * G1[:,1]   (real coefficients: ry|0> = (c, s))
    u1[0].re = c1 * C[8] + s1 * C[10];  u1[0].im = c1 * C[9] + s1 * C[11];
    u1[1].re = c1 * C[12] + s1 * C[14]; u1[1].im = c1 * C[13] + s1 * C[15];
    u2[0].re = C[16]; u2[0].im = C[17];
    u2[1].re = C[18]; u2[1].im = C[19];
    u3[0].re = c3 * C[20] + s3 * C[23]; u3[0].im = c3 * C[21] - s3 * C[22];
    u3[1].re = c3 * C[24] + s3 * C[27]; u3[1].im = c3 * C[25] - s3 * C[26];

    // psi[i] with i = 8*b0 + 4*b1 + 2*b2 + b3 (wire 0 = MSB)
    Cpx t01[4], t23[4];
    #pragma unroll
    for (int a = 0; a < 2; a++)
        #pragma unroll
        for (int b = 0; b < 2; b++) {
            t01[a * 2 + b] = cmul(u0[a], u1[b]);
            t23[a * 2 + b] = cmul(u2[a], u3[b]);
        }
    Cpx psi[16];
    #pragma unroll
    for (int i = 0; i < 16; i++)
        psi[i] = cmul(t01[i >> 2], t23[i & 3]);

    // CNOT ring (0,1)(1,2)(2,3)(3,0): phi[i] = psi[perm[i]]
    const int perm[16] = {0, 13, 3, 14, 6, 11, 5, 8, 12, 1, 15, 2, 10, 7, 9, 4};
    Cpx phi[16];
    #pragma unroll
    for (int i = 0; i < 16; i++) phi[i] = psi[perm[i]];

    // Final rx(theta[12+q]) on wire q. Wire q stride = 8 >> q.
    #pragma unroll
    for (int q = 0; q < 4; q++) {
        const int stride = 8 >> q;
        const float cf = C[28 + 2 * q];
        const float sf = C[29 + 2 * q];
        #pragma unroll
        for (int i = 0; i < 16; i++) {
            if (i & stride) continue;
            Cpx a = phi[i], b = phi[i + stride];
            phi[i].re          = cf * a.re + sf * b.im;
            phi[i].im          = cf * a.im - sf * b.re;
            phi[i + stride].re = cf * b.re + sf * a.im;
            phi[i + stride].im = cf * b.im - sf * a.re;
        }
    }

    // probs and signed reductions
    float p[16];
    #pragma unroll
    for (int i = 0; i < 16; i++)
        p[i] = phi[i].re * phi[i].re + phi[i].im * phi[i].im;

    float s1a[8], z3 = 0.0f;
    #pragma unroll
    for (int j = 0; j < 8; j++) {
        s1a[j] = p[2 * j] + p[2 * j + 1];
        z3 += p[2 * j] - p[2 * j + 1];
    }
    float s2a[4], z2 = 0.0f;
    #pragma unroll
    for (int k = 0; k < 4; k++) {
        s2a[k] = s1a[2 * k] + s1a[2 * k + 1];
        z2 += s1a[2 * k] - s1a[2 * k + 1];
    }
    float z1 = (s2a[0] - s2a[1]) + (s2a[2] - s2a[3]);
    float z0 = (s2a[0] + s2a[1]) - (s2a[2] + s2a[3]);

    float4 o;
    o.x = z0; o.y = z1; o.z = z2; o.w = z3;
    out[tid] = o;
}

extern "C" void kernel_launch(void* const* d_in, const int* in_sizes, int n_in,
                              void* d_out, int out_size) {
    const float* inputs = (const float*)d_in[0];   // [B, 4] float32
    const float* theta  = (const float*)d_in[1];   // [16] float32
    float* out = (float*)d_out;                    // [B, 4, 1] float32

    int n = in_sizes[0] / 4;  // number of samples

    precompute_kernel<<<1, 32>>>(theta);

    int threads = 256;
    int blocks = (n + threads - 1) / threads;
    qsim_kernel<<<blocks, threads>>>((const float4*)inputs, (float4*)out, n);
}

// round 2
// speedup vs baseline: 1.0233x; 1.0233x over previous
#include <cuda_runtime.h>

// ---------------------------------------------------------------------------
// QuantumHybridHead: 4-qubit circuit, B=524288 samples.
// Per sample: |psi> = kron(u0(w0), u1(w1), u2_const, u3(w3)) where
//   u_q = G_q * (encoder_q |0>), G_q = Rz(th[3q+2]) Ry(th[3q+1]) Rx(th[3q]).
// Wire-2 encoder rz is a global phase on |0> -> dead input.
// CNOT ring = static permutation of 16 basis amplitudes.
// Final per-wire rx(th[12+q]) gates, then <Z_w> from probabilities.
// ---------------------------------------------------------------------------

struct Cpx { float re, im; };

__device__ __forceinline__ Cpx cmul(Cpx a, Cpx b) {
    Cpx r;
    r.re = a.re * b.re - a.im * b.im;
    r.im = a.re * b.im + a.im * b.re;
    return r;
}

// Constant table computed from theta on-device:
// [0..7]   G0: g00.re g00.im g01.re g01.im g10.re g10.im g11.re g11.im
// [8..15]  G1 (same layout)
// [16..19] u2 = G2[:,0]: re im re im
// [20..27] G3
// [28..35] (cf, sf) for final rx on wires 0..3
__device__ float d_const[36];

__global__ void precompute_kernel(const float* __restrict__ theta) {
    if (threadIdx.x != 0 || blockIdx.x != 0) return;
    float G[4][8];
    #pragma unroll
    for (int q = 0; q < 4; q++) {
        float tx = theta[3 * q + 0];
        float ty = theta[3 * q + 1];
        float tz = theta[3 * q + 2];
        float cx, sx, cy, sy, cz, sz;
        sincosf(0.5f * tx, &sx, &cx);
        sincosf(0.5f * ty, &sy, &cy);
        sincosf(0.5f * tz, &sz, &cz);
        // M = Ry * Rx
        Cpx m00 = { cy * cx,  sy * sx };
        Cpx m01 = { -sy * cx, -cy * sx };
        Cpx m10 = { sy * cx,  -cy * sx };
        Cpx m11 = { cy * cx,  -sy * sx };
        // G = Rz * M ; Rz = diag(e^{-iz/2}, e^{+iz/2})
        Cpx e0 = { cz, -sz };
        Cpx e1 = { cz,  sz };
        Cpx g00 = cmul(e0, m00), g01 = cmul(e0, m01);
        Cpx g10 = cmul(e1, m10), g11 = cmul(e1, m11);
        G[q][0] = g00.re; G[q][1] = g00.im; G[q][2] = g01.re; G[q][3] = g01.im;
        G[q][4] = g10.re; G[q][5] = g10.im; G[q][6] = g11.re; G[q][7] = g11.im;
    }
    #pragma unroll
    for (int k = 0; k < 8; k++) d_const[k] = G[0][k];
    #pragma unroll
    for (int k = 0; k < 8; k++) d_const[8 + k] = G[1][k];
    // u2 = first column of G2 (wire-2 encoder is identity up to global phase)
    d_const[16] = G[2][0]; d_const[17] = G[2][1];
    d_const[18] = G[2][4]; d_const[19] = G[2][5];
    #pragma unroll
    for (int k = 0; k < 8; k++) d_const[20 + k] = G[3][k];
    #pragma unroll
    for (int q = 0; q < 4; q++) {
        float c, s;
        sincosf(0.5f * theta[12 + q], &s, &c);
        d_const[28 + 2 * q] = c;
        d_const[29 + 2 * q] = s;
    }
}

__global__ void __launch_bounds__(256)
qsim_kernel(const float4* __restrict__ inp, float4* __restrict__ out, int n) {
    int tid = blockIdx.x * blockDim.x + threadIdx.x;
    if (tid >= n) return;

    float C[36];
    #pragma unroll
    for (int k = 0; k < 36; k++) C[k] = d_const[k];

    float4 w = inp[tid];
    float c0, s0, c1, s1, c3, s3;
    __sincosf(0.5f * w.x, &s0, &c0);
    __sincosf(0.5f * w.y, &s1, &c1);
    __sincosf(0.5f * w.w, &s3, &c3);
    // w.z (wire-2 rz on |0>) is a global phase: dead.

    // Per-wire post-G vectors.
    // u0 = c0 * G0[:,0] + (-i s0) * G0[:,1]
    Cpx u0[2], u1[2], u2[2], u3[2];
    u0[0].re = c0 * C[0] + s0 * C[3];   u0[0].im = c0 * C[1] - s0 * C[2];
    u0[1].re = c0 * C[4] + s0 * C[7];   u0[1].im = c0 * C[5] - s0 * C[6];
    // u1 = c1 * G1[:,0] + s1 * G1[:,1]   (real coefficients: ry|0> = (c, s))
    u1[0].re = c1 * C[8] + s1 * C[10];  u1[0].im = c1 * C[9] + s1 * C[11];
    u1[1].re = c1 * C[12] + s1 * C[14]; u1[1].im = c1 * C[13] + s1 * C[15];
    u2[0].re = C[16]; u2[0].im = C[17];
    u2[1].re = C[18]; u2[1].im = C[19];
    u3[0].re = c3 * C[20] + s3 * C[23]; u3[0].im = c3 * C[21] - s3 * C[22];
    u3[1].re = c3 * C[24] + s3 * C[27]; u3[1].im = c3 * C[25] - s3 * C[26];

    // psi[i] with i = 8*b0 + 4*b1 + 2*b2 + b3 (wire 0 = MSB)
    Cpx t01[4], t23[4];
    #pragma unroll
    for (int a = 0; a < 2; a++)
        #pragma unroll
        for (int b = 0; b < 2; b++) {
            t01[a * 2 + b] = cmul(u0[a], u1[b]);
            t23[a * 2 + b] = cmul(u2[a], u3[b]);
        }
    Cpx psi[16];
    #pragma unroll
    for (int i = 0; i < 16; i++)
        psi[i] = cmul(t01[i >> 2], t23[i & 3]);

    // CNOT ring (0,1)(1,2)(2,3)(3,0): phi[i] = psi[perm[i]]
    const int perm[16] = {0, 13, 3, 14, 6, 11, 5, 8, 12, 1, 15, 2, 10, 7, 9, 4};
    Cpx phi[16];
    #pragma unroll
    for (int i = 0; i < 16; i++) phi[i] = psi[perm[i]];

    // Final rx(theta[12+q]) on wire q. Wire q stride = 8 >> q.
    #pragma unroll
    for (int q = 0; q < 4; q++) {
        const int stride = 8 >> q;
        const float cf = C[28 + 2 * q];
        const float sf = C[29 + 2 * q];
        #pragma unroll
        for (int i = 0; i < 16; i++) {
            if (i & stride) continue;
            Cpx a = phi[i], b = phi[i + stride];
            phi[i].re          = cf * a.re + sf * b.im;
            phi[i].im          = cf * a.im - sf * b.re;
            phi[i + stride].re = cf * b.re + sf * a.im;
            phi[i + stride].im = cf * b.im - sf * a.re;
        }
    }

    // probs and signed reductions
    float p[16];
    #pragma unroll
    for (int i = 0; i < 16; i++)
        p[i] = phi[i].re * phi[i].re + phi[i].im * phi[i].im;

    float s1a[8], z3 = 0.0f;
    #pragma unroll
    for (int j = 0; j < 8; j++) {
        s1a[j] = p[2 * j] + p[2 * j + 1];
        z3 += p[2 * j] - p[2 * j + 1];
    }
    float s2a[4], z2 = 0.0f;
    #pragma unroll
    for (int k = 0; k < 4; k++) {
        s2a[k] = s1a[2 * k] + s1a[2 * k + 1];
        z2 += s1a[2 * k] - s1a[2 * k + 1];
    }
    float z1 = (s2a[0] - s2a[1]) + (s2a[2] - s2a[3]);
    float z0 = (s2a[0] + s2a[1]) - (s2a[2] + s2a[3]);

    float4 o;
    o.x = z0; o.y = z1; o.z = z2; o.w = z3;
    out[tid] = o;
}

extern "C" void kernel_launch(void* const* d_in, const int* in_sizes, int n_in,
                              void* d_out, int out_size) {
    const float* inputs = (const float*)d_in[0];   // [B, 4] float32
    const float* theta  = (const float*)d_in[1];   // [16] float32
    float* out = (float*)d_out;                    // [B, 4, 1] float32

    int n = in_sizes[0] / 4;  // number of samples

    precompute_kernel<<<1, 32>>>(theta);

    int threads = 256;
    int blocks = (n + threads - 1) / threads;
    qsim_kernel<<<blocks, threads>>>((const float4*)inputs, (float4*)out, n);
}

// round 3
// speedup vs baseline: 2.0465x; 2.0000x over previous
#include <cuda_runtime.h>

// ---------------------------------------------------------------------------
// QuantumHybridHead, Heisenberg-picture reduction.
// psi = u0 (x) u1 (x) u2 (x) u3  (product state; u2 constant, wire-2 input dead)
// z_w = <psi| P^dag (cos t_w Z_w + sin t_w Y_w) P |psi>,  P = CNOT ring.
// Conjugated Pauli strings (derived, Z-parts verified by bit propagation):
//   z0 = c0 <Z1 Z2 Z3> + s0 <X0 Y1 Z2 Z3>
//   z1 = c1 <Z0 Z1>    + s1 <Z0 Y1 X2>
//   z2 = c2 <Z0 Z1 Z2> + s2 <Z0 Z1 Y2 X3>
//   z3 = c3 <Z0Z1Z2Z3> - s3 <Y0 Y1 Z2 Y3>
// Product state => string expectation = product of per-wire Pauli expectations.
// Per-wire expectation: E(w) = p + q*cos(w) + r*sin(w)   (w = full input angle)
// where u = cos(w/2) g0 + sin(w/2) k g1, k = -i (rx enc) or 1 (ry enc),
//   p=(A+B)/2, q=(A-B)/2, r=Re(k * g0^dag sigma g1), A=g0^dag s g0, B=g1^dag s g1.
// Wire-2 expectations are constants folded into the 8 output coefficients.
// ---------------------------------------------------------------------------

struct Cpx { float re, im; };

__device__ __forceinline__ Cpx cmul(Cpx a, Cpx b) {
    return { a.re * b.re - a.im * b.im, a.re * b.im + a.im * b.re };
}
__device__ __forceinline__ Cpx cconjmul(Cpx a, Cpx b) {  // conj(a)*b
    return { a.re * b.re + a.im * b.im, a.re * b.im - a.im * b.re };
}

// G = Rz(th[2]) * Ry(th[1]) * Rx(th[0])
__device__ __forceinline__ void gateG(const float* __restrict__ th,
                                      Cpx& g00, Cpx& g01, Cpx& g10, Cpx& g11) {
    float cx, sx, cy, sy, cz, sz;
    __sincosf(0.5f * th[0], &sx, &cx);
    __sincosf(0.5f * th[1], &sy, &cy);
    __sincosf(0.5f * th[2], &sz, &cz);
    Cpx m00 = { cy * cx,  sy * sx };
    Cpx m01 = { -sy * cx, -cy * sx };
    Cpx m10 = { sy * cx,  -cy * sx };
    Cpx m11 = { cy * cx,  -sy * sx };
    Cpx e0 = { cz, -sz };
    Cpx e1 = { cz,  sz };
    g00 = cmul(e0, m00); g01 = cmul(e0, m01);
    g10 = cmul(e1, m10); g11 = cmul(e1, m11);
}

// tmp[0..8] = pZ qZ rZ pX qX rX pY qY rY
__device__ __forceinline__ void wireConsts(Cpx g00, Cpx g01, Cpx g10, Cpx g11,
                                           bool k_minus_i, float* tmp) {
    float n00 = g00.re * g00.re + g00.im * g00.im;
    float n01 = g01.re * g01.re + g01.im * g01.im;
    float n10 = g10.re * g10.re + g10.im * g10.im;
    float n11 = g11.re * g11.re + g11.im * g11.im;
    // Z
    float AZ = n00 - n10, BZ = n01 - n11;
    Cpx a01 = cconjmul(g00, g01);   // conj(g00) g01
    Cpx b01 = cconjmul(g10, g11);   // conj(g10) g11
    Cpx CZ = { a01.re - b01.re, a01.im - b01.im };
    // X
    Cpx c00 = cconjmul(g00, g10);   // conj(g00) g10
    Cpx c01 = cconjmul(g01, g11);   // conj(g01) g11
    float AX = 2.0f * c00.re, BX = 2.0f * c01.re;
    Cpx t1 = cconjmul(g00, g11);    // conj(g00) g11
    Cpx t2 = cconjmul(g10, g01);    // conj(g10) g01
    Cpx CX = { t1.re + t2.re, t1.im + t2.im };
    // Y
    float AY = 2.0f * c00.im, BY = 2.0f * c01.im;
    Cpx D = { t2.re - t1.re, t2.im - t1.im };   // conj(g10)g01 - conj(g00)g11
    Cpx CY = { -D.im, D.re };                   // i*D
    tmp[0] = 0.5f * (AZ + BZ); tmp[1] = 0.5f * (AZ - BZ);
    tmp[2] = k_minus_i ? CZ.im : CZ.re;
    tmp[3] = 0.5f * (AX + BX); tmp[4] = 0.5f * (AX - BX);
    tmp[5] = k_minus_i ? CX.im : CX.re;
    tmp[6] = 0.5f * (AY + BY); tmp[7] = 0.5f * (AY - BY);
    tmp[8] = k_minus_i ? CY.im : CY.re;
}

// Const layout:
//  [0..8]   wire0: Z(p,q,r) X(p,q,r) Y(p,q,r)
//  [9..14]  wire1: Z(p,q,r) Y(p,q,r)
//  [15..23] wire3: Z(p,q,r) X(p,q,r) Y(p,q,r)
//  [24..31] A0 B0 A1 B1 A2a A2b A3 B3
__device__ __forceinline__ float4 sample(const float* __restrict__ C, float4 w) {
    float cw0, sw0, cw1, sw1, cw3, sw3;
    __sincosf(w.x, &sw0, &cw0);
    __sincosf(w.y, &sw1, &cw1);
    __sincosf(w.w, &sw3, &cw3);
    float z0 = fmaf(C[1],  cw0, fmaf(C[2],  sw0, C[0]));
    float x0 = fmaf(C[4],  cw0, fmaf(C[5],  sw0, C[3]));
    float y0 = fmaf(C[7],  cw0, fmaf(C[8],  sw0, C[6]));
    float z1 = fmaf(C[10], cw1, fmaf(C[11], sw1, C[9]));
    float y1 = fmaf(C[13], cw1, fmaf(C[14], sw1, C[12]));
    float z3 = fmaf(C[16], cw3, fmaf(C[17], sw3, C[15]));
    float x3 = fmaf(C[19], cw3, fmaf(C[20], sw3, C[18]));
    float y3 = fmaf(C[22], cw3, fmaf(C[23], sw3, C[21]));
    float z01 = z0 * z1;
    float4 o;
    o.x = z3  * fmaf(C[25], x0 * y1, C[24] * z1);
    o.y = z0  * fmaf(C[27], y1,      C[26] * z1);
    o.z = z01 * fmaf(C[29], x3,      C[28]);
    o.w = fmaf(C[30], z01 * z3, -(C[31] * (y0 * y1) * y3));
    return o;
}

__global__ void __launch_bounds__(256)
qsim_kernel(const float4* __restrict__ inp, const float* __restrict__ theta,
            float4* __restrict__ out, int n, int half) {
    __shared__ float sc[32];
    int t = threadIdx.x;

    if (t < 4) {
        if (t < 3) {
            // t=0 -> wire0 (rx enc), t=1 -> wire1 (ry enc), t=2 -> wire3 (rx enc)
            int q = (t == 2) ? 3 : t;
            Cpx g00, g01, g10, g11;
            gateG(theta + 3 * q, g00, g01, g10, g11);
            float tmp[9];
            wireConsts(g00, g01, g10, g11, t != 1, tmp);
            if (t == 0) {
                #pragma unroll
                for (int k = 0; k < 9; k++) sc[k] = tmp[k];
            } else if (t == 1) {
                sc[9]  = tmp[0]; sc[10] = tmp[1]; sc[11] = tmp[2];
                sc[12] = tmp[6]; sc[13] = tmp[7]; sc[14] = tmp[8];
            } else {
                #pragma unroll
                for (int k = 0; k < 9; k++) sc[15 + k] = tmp[k];
            }
        } else {
            // t=3: wire-2 constant expectations + final-rx folds
            Cpx g00, g01, g10, g11;
            gateG(theta + 6, g00, g01, g10, g11);
            // u2 = G2 |0> = (g00, g10)
            float z2c = (g00.re * g00.re + g00.im * g00.im)
                      - (g10.re * g10.re + g10.im * g10.im);
            Cpx cr = cconjmul(g00, g10);
            float x2c = 2.0f * cr.re;
            float y2c = 2.0f * cr.im;
            float cw[4], sw[4];
            #pragma unroll
            for (int q = 0; q < 4; q++) __sincosf(theta[12 + q], &sw[q], &cw[q]);
            sc[24] = cw[0] * z2c;  // A0
            sc[25] = sw[0] * z2c;  // B0
            sc[26] = cw[1];        // A1
            sc[27] = sw[1] * x2c;  // B1
            sc[28] = cw[2] * z2c;  // A2a
            sc[29] = sw[2] * y2c;  // A2b
            sc[30] = cw[3] * z2c;  // A3
            sc[31] = sw[3] * z2c;  // B3
        }
    }
    __syncthreads();

    float C[32];
    #pragma unroll
    for (int k = 0; k < 32; k++) C[k] = sc[k];

    int tid = blockIdx.x * blockDim.x + threadIdx.x;
    int i0 = tid;
    int i1 = tid + half;
    if (i0 < n) {
        float4 w0 = inp[i0];
        float4 w1;
        bool do1 = (i1 < n);
        if (do1) w1 = inp[i1];
        float4 o0 = sample(C, w0);
        out[i0] = o0;
        if (do1) {
            float4 o1 = sample(C, w1);
            out[i1] = o1;
        }
    }
}

extern "C" void kernel_launch(void* const* d_in, const int* in_sizes, int n_in,
                              void* d_out, int out_size) {
    const float* inputs = (const float*)d_in[0];   // [B, 4] float32
    const float* theta  = (const float*)d_in[1];   // [16] float32
    float* out = (float*)d_out;                    // [B, 4, 1] float32

    int n = in_sizes[0] / 4;        // samples
    int half = (n + 1) / 2;         // samples handled by the first lane index
    int threads = 256;
    int blocks = (half + threads - 1) / threads;

    qsim_kernel<<<blocks, threads>>>((const float4*)inputs, theta,
                                     (float4*)out, n, half);
}

// round 4
// speedup vs baseline: 2.5631x; 1.2524x over previous
#include <cuda_runtime.h>

// ---------------------------------------------------------------------------
// QuantumHybridHead, Heisenberg-picture reduction (see R2 derivation).
// z0 = c0 <Z1 Z2 Z3> + s0 <X0 Y1 Z2 Z3>
// z1 = c1 <Z0 Z1>    + s1 <Z0 Y1 X2>
// z2 = c2 <Z0 Z1 Z2> + s2 <Z0 Z1 Y2 X3>
// z3 = c3 <Z0Z1Z2Z3> - s3 <Y0 Y1 Z2 Y3>
// Product state => per-wire affine expectations E(w) = p + q cos w + r sin w.
// This round: 4 samples/thread with front-batched loads so the per-block
// constant-precompute chain + barrier hide under DRAM latency (MLP=4).
// ---------------------------------------------------------------------------

struct Cpx { float re, im; };

__device__ __forceinline__ Cpx cmul(Cpx a, Cpx b) {
    return { a.re * b.re - a.im * b.im, a.re * b.im + a.im * b.re };
}
__device__ __forceinline__ Cpx cconjmul(Cpx a, Cpx b) {  // conj(a)*b
    return { a.re * b.re + a.im * b.im, a.re * b.im - a.im * b.re };
}

// G = Rz(th[2]) * Ry(th[1]) * Rx(th[0])
__device__ __forceinline__ void gateG(const float* __restrict__ th,
                                      Cpx& g00, Cpx& g01, Cpx& g10, Cpx& g11) {
    float cx, sx, cy, sy, cz, sz;
    __sincosf(0.5f * th[0], &sx, &cx);
    __sincosf(0.5f * th[1], &sy, &cy);
    __sincosf(0.5f * th[2], &sz, &cz);
    Cpx m00 = { cy * cx,  sy * sx };
    Cpx m01 = { -sy * cx, -cy * sx };
    Cpx m10 = { sy * cx,  -cy * sx };
    Cpx m11 = { cy * cx,  -sy * sx };
    Cpx e0 = { cz, -sz };
    Cpx e1 = { cz,  sz };
    g00 = cmul(e0, m00); g01 = cmul(e0, m01);
    g10 = cmul(e1, m10); g11 = cmul(e1, m11);
}

// tmp[0..8] = pZ qZ rZ pX qX rX pY qY rY
__device__ __forceinline__ void wireConsts(Cpx g00, Cpx g01, Cpx g10, Cpx g11,
                                           bool k_minus_i, float* tmp) {
    float n00 = g00.re * g00.re + g00.im * g00.im;
    float n01 = g01.re * g01.re + g01.im * g01.im;
    float n10 = g10.re * g10.re + g10.im * g10.im;
    float n11 = g11.re * g11.re + g11.im * g11.im;
    float AZ = n00 - n10, BZ = n01 - n11;
    Cpx a01 = cconjmul(g00, g01);
    Cpx b01 = cconjmul(g10, g11);
    Cpx CZ = { a01.re - b01.re, a01.im - b01.im };
    Cpx c00 = cconjmul(g00, g10);
    Cpx c01 = cconjmul(g01, g11);
    float AX = 2.0f * c00.re, BX = 2.0f * c01.re;
    Cpx t1 = cconjmul(g00, g11);
    Cpx t2 = cconjmul(g10, g01);
    Cpx CX = { t1.re + t2.re, t1.im + t2.im };
    float AY = 2.0f * c00.im, BY = 2.0f * c01.im;
    Cpx D = { t2.re - t1.re, t2.im - t1.im };
    Cpx CY = { -D.im, D.re };                   // i*D
    tmp[0] = 0.5f * (AZ + BZ); tmp[1] = 0.5f * (AZ - BZ);
    tmp[2] = k_minus_i ? CZ.im : CZ.re;
    tmp[3] = 0.5f * (AX + BX); tmp[4] = 0.5f * (AX - BX);
    tmp[5] = k_minus_i ? CX.im : CX.re;
    tmp[6] = 0.5f * (AY + BY); tmp[7] = 0.5f * (AY - BY);
    tmp[8] = k_minus_i ? CY.im : CY.re;
}

// Const layout:
//  [0..8]   wire0: Z(p,q,r) X(p,q,r) Y(p,q,r)
//  [9..14]  wire1: Z(p,q,r) Y(p,q,r)
//  [15..23] wire3: Z(p,q,r) X(p,q,r) Y(p,q,r)
//  [24..31] A0 B0 A1 B1 A2a A2b A3 B3
__device__ __forceinline__ float4 sample(const float* __restrict__ C, float4 w) {
    float cw0, sw0, cw1, sw1, cw3, sw3;
    __sincosf(w.x, &sw0, &cw0);
    __sincosf(w.y, &sw1, &cw1);
    __sincosf(w.w, &sw3, &cw3);
    float z0 = fmaf(C[1],  cw0, fmaf(C[2],  sw0, C[0]));
    float x0 = fmaf(C[4],  cw0, fmaf(C[5],  sw0, C[3]));
    float y0 = fmaf(C[7],  cw0, fmaf(C[8],  sw0, C[6]));
    float z1 = fmaf(C[10], cw1, fmaf(C[11], sw1, C[9]));
    float y1 = fmaf(C[13], cw1, fmaf(C[14], sw1, C[12]));
    float z3 = fmaf(C[16], cw3, fmaf(C[17], sw3, C[15]));
    float x3 = fmaf(C[19], cw3, fmaf(C[20], sw3, C[18]));
    float y3 = fmaf(C[22], cw3, fmaf(C[23], sw3, C[21]));
    float z01 = z0 * z1;
    float4 o;
    o.x = z3  * fmaf(C[25], x0 * y1, C[24] * z1);
    o.y = z0  * fmaf(C[27], y1,      C[26] * z1);
    o.z = z01 * fmaf(C[29], x3,      C[28]);
    o.w = fmaf(C[30], z01 * z3, -(C[31] * (y0 * y1) * y3));
    return o;
}

static constexpr int SPT = 4;  // samples per thread

__global__ void __launch_bounds__(256)
qsim_kernel(const float4* __restrict__ inp, const float* __restrict__ theta,
            float4* __restrict__ out, int n, int nthreads) {
    __shared__ float sc[32];
    int t = threadIdx.x;
    int tid = blockIdx.x * blockDim.x + t;

    // ---- Front-batch the 4 input loads: independent of the constants, so
    // they fly while the precompute chain + barrier resolve. ----
    float4 w[SPT];
    int idx[SPT];
    bool ok[SPT];
    #pragma unroll
    for (int k = 0; k < SPT; k++) {
        idx[k] = tid + k * nthreads;
        ok[k] = idx[k] < n;
        if (ok[k]) w[k] = inp[idx[k]];
    }

    // ---- Per-block constant precompute (threads 0..3) ----
    if (t < 4) {
        if (t < 3) {
            int q = (t == 2) ? 3 : t;
            Cpx g00, g01, g10, g11;
            gateG(theta + 3 * q, g00, g01, g10, g11);
            float tmp[9];
            wireConsts(g00, g01, g10, g11, t != 1, tmp);
            if (t == 0) {
                #pragma unroll
                for (int k = 0; k < 9; k++) sc[k] = tmp[k];
            } else if (t == 1) {
                sc[9]  = tmp[0]; sc[10] = tmp[1]; sc[11] = tmp[2];
                sc[12] = tmp[6]; sc[13] = tmp[7]; sc[14] = tmp[8];
            } else {
                #pragma unroll
                for (int k = 0; k < 9; k++) sc[15 + k] = tmp[k];
            }
        } else {
            Cpx g00, g01, g10, g11;
            gateG(theta + 6, g00, g01, g10, g11);
            // u2 = G2 |0> = (g00, g10)
            float z2c = (g00.re * g00.re + g00.im * g00.im)
                      - (g10.re * g10.re + g10.im * g10.im);
            Cpx cr = cconjmul(g00, g10);
            float x2c = 2.0f * cr.re;
            float y2c = 2.0f * cr.im;
            float cw[4], sw[4];
            #pragma unroll
            for (int q = 0; q < 4; q++) __sincosf(theta[12 + q], &sw[q], &cw[q]);
            sc[24] = cw[0] * z2c;  // A0
            sc[25] = sw[0] * z2c;  // B0
            sc[26] = cw[1];        // A1
            sc[27] = sw[1] * x2c;  // B1
            sc[28] = cw[2] * z2c;  // A2a
            sc[29] = sw[2] * y2c;  // A2b
            sc[30] = cw[3] * z2c;  // A3
            sc[31] = sw[3] * z2c;  // B3
        }
    }
    __syncthreads();

    float C[32];
    #pragma unroll
    for (int k = 0; k < 32; k++) C[k] = sc[k];

    // ---- Compute + store per sample (store issued immediately) ----
    #pragma unroll
    for (int k = 0; k < SPT; k++) {
        if (ok[k]) {
            float4 o = sample(C, w[k]);
            out[idx[k]] = o;
        }
    }
}

extern "C" void kernel_launch(void* const* d_in, const int* in_sizes, int n_in,
                              void* d_out, int out_size) {
    const float* inputs = (const float*)d_in[0];   // [B, 4] float32
    const float* theta  = (const float*)d_in[1];   // [16] float32
    float* out = (float*)d_out;                    // [B, 4, 1] float32

    int n = in_sizes[0] / 4;                 // samples
    int per = (n + SPT - 1) / SPT;           // samples per lane-index slot
    int threads = 256;
    int blocks = (per + threads - 1) / threads;
    int nthreads = blocks * threads;

    qsim_kernel<<<blocks, threads>>>((const float4*)inputs, theta,
                                     (float4*)out, n, nthreads);
}